// round 17
// baseline (speedup 1.0000x reference)
#include <cuda_runtime.h>
#include <math.h>
#include <stdint.h>

#define EPSN 1e-12f

// pack two f32 -> bf16x2 (lo = g0, hi = g1)
__device__ __forceinline__ uint32_t pack_bf16x2(float g1, float g0) {
    uint32_t r;
    asm("cvt.rn.bf16x2.f32 %0, %1, %2;" : "=r"(r) : "f"(g1), "f"(g0));
    return r;
}

__device__ __forceinline__ void mma_bf16(float* c, const uint32_t* a, const uint32_t* b) {
    asm("mma.sync.aligned.m16n8k16.row.col.f32.bf16.bf16.f32 "
        "{%0,%1,%2,%3}, {%4,%5,%6,%7}, {%8,%9}, {%0,%1,%2,%3};"
        : "+f"(c[0]), "+f"(c[1]), "+f"(c[2]), "+f"(c[3])
        : "r"(a[0]), "r"(a[1]), "r"(a[2]), "r"(a[3]), "r"(b[0]), "r"(b[1]));
}

// Banded cost volume via m16n8k16 bf16 MMA, 3xBF16 split (Ah*Bh + Ah*Bl + Al*Bh).
// One CTA = one (n, h, x-tile of 128). Channels in passes of CB=32 = 16 bf16x2
// channel-pair words per matrix.
//
// SMEM layout: uint2 pairs {hi_word, lo_word}, row stride CP=20 pairs, XOR
// swizzle p ^= (row>>2)&7. Bank geometry == the validated float2/CP=36 layout
// (20 = 4 mod 16): staging STS.64 AND fragment LDS.64 are both conflict-free
// per 16-lane phase, and each LDS.64 fetches the hi and lo words together.
//
// Per-column L2 norms accumulated in registers DURING staging (exact fp32),
// reduced through a small smem partial array at the end.
// 16 warps: warp w = (x-tile (w>>1)*16, j-half w&1), NJTH j-tiles each.
// Epilogue: normalize + mask, bounce through smem sOut (aliasing dead tiles)
// in NDR d-rounds, then coalesced streaming float4 stores.

template<int C, int D, int N, int NDR>
__device__ __forceinline__ void cv_level(const float* __restrict__ Lp,
                                         const float* __restrict__ Rp,
                                         float* __restrict__ out,
                                         int H, int W, int bx, int h, int n,
                                         char* smem)
{
    constexpr int TX = 128, NT = 512, CB = 32, CP = 20;
    constexpr int NJT  = (D + 22) / 8;
    constexpr int NJTH = NJT / 2;
    constexpr int SOP  = TX + 4;
    constexpr int NPASS = C / CB;
    constexpr int DH = D / NDR;
    static_assert((NJT % 2) == 0, "even j-split");
    static_assert(8 * NJT >= D + 15, "band coverage");
    static_assert(112 + 8 * NJTH + 8 * NJTH - 1 <= N - 1, "halo bound");

    // pair-addressed tile map
    constexpr int OF_A   = 0;                    // TX*CP pairs
    constexpr int OF_B   = TX * CP;              // N*CP pairs
    constexpr int PAIRW  = 2 * CP * (TX + N);    // tile region in words
    constexpr int OF_INVL = PAIRW;               // float offsets
    constexpr int OF_INVR = PAIRW + TX;
    static_assert(DH * SOP <= PAIRW, "sOut alias fits");

    uint2* su = (uint2*)smem;
    float* sf = (float*)smem;

    const int tid  = threadIdx.x;
    const int wid  = tid >> 5;
    const int lane = tid & 31;
    const int gid  = lane >> 2;
    const int tig  = lane & 3;

    const int xb = bx * TX;
    const int HW = H * W;
    const int plane = ((n * C) * H + h) * W;
    const int y0 = xb - (D - 1);

    const int xw0     = (wid >> 1) * 16;
    const int colbase = xw0 + (wid & 1) * (8 * NJTH);

    // staging swizzle (pair index)
    #define SWP(row, p) ((row) * CP + ((p) ^ (((row) >> 2) & 7)))

    // ---- pass-invariant fragment pair-index bases ----
    const int rA0 = xw0 + gid, rA1 = rA0 + 8;
    const int pA0 = tig ^ ((rA0 >> 2) & 7);
    const int pA1 = tig ^ ((rA1 >> 2) & 7);
    const int iA0a = rA0 * CP + pA0,        iA0b = rA0 * CP + (pA0 ^ 4);
    const int iA1a = rA1 * CP + pA1,        iA1b = rA1 * CP + (pA1 ^ 4);

    const int rB0 = colbase + gid;
    const int oB0 = (rB0 >> 2) & 7;              // exact: colbase mult of 8
    int iBp[4], iBq[4];                          // swizzle period 4 in j-tile
    #pragma unroll
    for (int j = 0; j < 4; ++j) {
        int p = tig ^ ((oB0 + 2 * j) & 7);
        iBp[j] = rB0 * CP + p;
        iBq[j] = rB0 * CP + (p ^ 4);
    }

    float acc[NJTH][4];
    #pragma unroll
    for (int t = 0; t < NJTH; ++t)
        #pragma unroll
        for (int q = 0; q < 4; ++q) acc[t][q] = 0.0f;

    float ssA = 0.0f, ssB = 0.0f;

    // staging thread maps (pass-invariant => register ss accumulation)
    const int axc = tid & 127, agrp = tid >> 7;          // A: column, cp-group
    const int bactive = (tid < 2 * N);
    const int bcol = bactive ? (tid % N) : 0;
    const int bgrp = bactive ? (tid / N) : 0;
    const int by   = y0 + bcol;
    const int bok  = bactive && (by >= 0) && (by < W);

    #pragma unroll 1
    for (int pass = 0; pass < NPASS; ++pass) {
        if (pass) __syncthreads();
        const int cg = pass * CB;

        // ---- stage A (L tile): 4 channel-pairs per thread, STS.64 ----
        {
            const float* lp = Lp + plane + xb + axc + (size_t)cg * HW;
            #pragma unroll
            for (int j = 0; j < 4; ++j) {
                const int cp = agrp * 4 + j;
                float g0 = lp[(2 * cp) * HW];
                float g1 = lp[(2 * cp + 1) * HW];
                uint32_t hi = pack_bf16x2(g1, g0);
                float h0 = __uint_as_float(hi << 16);
                float h1 = __uint_as_float(hi & 0xFFFF0000u);
                uint32_t lo = pack_bf16x2(g1 - h1, g0 - h0);
                su[OF_A + SWP(axc, cp)] = make_uint2(hi, lo);
                ssA = fmaf(g0, g0, ssA);
                ssA = fmaf(g1, g1, ssA);
            }
        }
        // ---- stage B (R halo): 8 channel-pairs per active thread ----
        if (bactive) {
            const float* rp = Rp + plane + by + (size_t)cg * HW;
            #pragma unroll
            for (int j = 0; j < 8; ++j) {
                const int cp = bgrp * 8 + j;
                float g0 = bok ? rp[(2 * cp) * HW] : 0.0f;
                float g1 = bok ? rp[(2 * cp + 1) * HW] : 0.0f;
                uint32_t hi = pack_bf16x2(g1, g0);
                float h0 = __uint_as_float(hi << 16);
                float h1 = __uint_as_float(hi & 0xFFFF0000u);
                uint32_t lo = pack_bf16x2(g1 - h1, g0 - h0);
                su[OF_B + SWP(bcol, cp)] = make_uint2(hi, lo);
                ssB = fmaf(g0, g0, ssB);
                ssB = fmaf(g1, g1, ssB);
            }
        }
        __syncthreads();

        // ---- banded MMA sweep: 3xBF16 split, k16, conflict-free LDS.64 ----
        #pragma unroll
        for (int kc = 0; kc < 2; ++kc) {
            const int ko = kc * 8;               // +8 pairs: additive (bit3 free)
            uint2 va0 = su[iA0a + ko], va1 = su[iA1a + ko];
            uint2 vb0 = su[iA0b + ko], vb1 = su[iA1b + ko];
            uint32_t ah[4] = {va0.x, va1.x, vb0.x, vb1.x};
            uint32_t al[4] = {va0.y, va1.y, vb0.y, vb1.y};
            #pragma unroll
            for (int t = 0; t < NJTH; ++t) {
                const int tb = OF_B + t * 8 * CP + ko;   // compile-time constant
                uint2 w0 = su[iBp[t & 3] + tb];
                uint2 w1 = su[iBq[t & 3] + tb];
                uint32_t bh[2] = {w0.x, w1.x};
                uint32_t bl[2] = {w0.y, w1.y};
                mma_bf16(acc[t], ah, bh);
                mma_bf16(acc[t], ah, bl);
                mma_bf16(acc[t], al, bh);
            }
        }
    }

    // ---- reduce per-column norms through smem partials (alias dead tiles) ----
    __syncthreads();                     // MMA done reading tiles
    sf[tid] = ssA;                       // partA: words [0, 512)
    if (bactive) sf[512 + tid] = ssB;    // partB: words [512, 512 + 2N)
    __syncthreads();
    if (tid < TX) {
        float s = sf[tid] + sf[tid + 128] + sf[tid + 256] + sf[tid + 384];
        sf[OF_INVL + tid] = 1.0f / fmaxf(sqrtf(s), EPSN);
    }
    if (tid < N) {
        float s = sf[512 + tid] + sf[512 + tid + N];
        sf[OF_INVR + tid] = 1.0f / fmaxf(sqrtf(s), EPSN);
    }
    __syncthreads();

    // ---- epilogue: NDR d-rounds of normalize + mask + sOut bounce ----
    const int xl0 = xw0 + gid, xl8 = xl0 + 8;
    const float il0 = sf[OF_INVL + xl0], il8 = sf[OF_INVL + xl8];

    #pragma unroll
    for (int r = 0; r < NDR; ++r) {
        const int dlo = r * DH;
        #pragma unroll
        for (int t = 0; t < NJTH; ++t) {
            const int col0 = colbase + 8 * t + 2 * tig;
            const int col1 = col0 + 1;
            const float ir0 = sf[OF_INVR + col0], ir1 = sf[OF_INVR + col1];
            int d;
            d = xl0 + (D - 1) - col0;
            if (d >= dlo && d < dlo + DH)
                sf[(d - dlo) * SOP + xl0] = (xb + xl0 >= d) ? acc[t][0] * il0 * ir0 : 0.0f;
            d = xl0 + (D - 1) - col1;
            if (d >= dlo && d < dlo + DH)
                sf[(d - dlo) * SOP + xl0] = (xb + xl0 >= d) ? acc[t][1] * il0 * ir1 : 0.0f;
            d = xl8 + (D - 1) - col0;
            if (d >= dlo && d < dlo + DH)
                sf[(d - dlo) * SOP + xl8] = (xb + xl8 >= d) ? acc[t][2] * il8 * ir0 : 0.0f;
            d = xl8 + (D - 1) - col1;
            if (d >= dlo && d < dlo + DH)
                sf[(d - dlo) * SOP + xl8] = (xb + xl8 >= d) ? acc[t][3] * il8 * ir1 : 0.0f;
        }
        __syncthreads();

        #pragma unroll 1
        for (int idx = tid; idx < DH * (TX / 4); idx += NT) {
            int d = idx >> 5, q = idx & 31;
            float4 v = *(float4*)&sf[d * SOP + 4 * q];
            __stcs((float4*)&out[(((size_t)n * D + dlo + d) * H + h) * W + xb + 4 * q], v);
        }
        __syncthreads();
    }
    #undef SWP
}

// Fused launch: all three pyramid levels in one grid.
// Long blocks (L1: 2 passes, L2: 3 passes) first; L0 fills in.
//   [0, 512):    level 1  (bx in {0,1}, H=128, n in {0,1})
//   [512, 640):  level 2  (bx=0, H=64)
//   [640, 2688): level 0  (bx in 0..3, H=256)
__global__ __launch_bounds__(512, 2)
void cv_fused_kernel(const float* __restrict__ l0, const float* __restrict__ r0,
                     const float* __restrict__ l1, const float* __restrict__ r1,
                     const float* __restrict__ l2, const float* __restrict__ r2,
                     float* __restrict__ o0, float* __restrict__ o1,
                     float* __restrict__ o2)
{
    extern __shared__ __align__(16) char smem[];
    const int b = blockIdx.x;
    if (b >= 640) {
        const int bb = b - 640;
        cv_level<32, 128, 256, 2>(l0, r0, o0, 256, 512, bb & 3, (bb >> 2) & 255, bb >> 10, smem);
    } else if (b < 512) {
        cv_level<64, 64, 192, 1>(l1, r1, o1, 128, 256, b & 1, (b >> 1) & 127, b >> 8, smem);
    } else {
        const int bb = b - 512;
        cv_level<96, 32, 160, 1>(l2, r2, o2, 64, 128, 0, bb & 63, bb >> 6, smem);
    }
}

extern "C" void kernel_launch(void* const* d_in, const int* in_sizes, int n_in,
                              void* d_out, int out_size)
{
    const float* l0 = (const float*)d_in[0];
    const float* r0 = (const float*)d_in[1];
    const float* l1 = (const float*)d_in[2];
    const float* r1 = (const float*)d_in[3];
    const float* l2 = (const float*)d_in[4];
    const float* r2 = (const float*)d_in[5];
    float* out = (float*)d_out;

    // max_disparity = 128 (fixed by setup_inputs); per-level D = 128, 64, 32.
    float* out1 = out + (size_t)2 * 128 * 256 * 512;
    float* out2 = out1 + (size_t)2 * 64 * 128 * 256;

    // smem = level-0 requirement (max): 2*20*(128+256) words tiles + inv arrays
    constexpr int SMB = (2 * 20 * (128 + 256) + 128 + 256) * 4;  // 62976 B
    cudaFuncSetAttribute(cv_fused_kernel,
                         cudaFuncAttributeMaxDynamicSharedMemorySize, SMB);
    cv_fused_kernel<<<2688, 512, SMB>>>(l0, r0, l1, r1, l2, r2, out, out1, out2);
}